// round 9
// baseline (speedup 1.0000x reference)
#include <cuda_runtime.h>
#include <math.h>

#define NFRAMES 16
#define IMG_H   480
#define IMG_W   640
#define NCH     20
#define PLANE   (IMG_H * IMG_W)
#define DS_H    120
#define DS_W    160
#define NPIX    (DS_H * DS_W)
#define VR      100
#define CELLS   (VR * VR)
#define HALF    (CELLS / 2)
#define NSEM    16
#define NOUT    (2 + NSEM)
#define MIN_MAPPED 13
#define MAX_MAPPED 25

// Planar-by-group accumulators. Statically zero-initialized; finalize restores
// zeros each launch (invariant: acc is all-zero on entry to kernel_launch).
__device__ float4 g_sem[NFRAMES][4][CELLS];   // [g] = sem channels 4g..4g+3
__device__ float  g_ind[NFRAMES][2][CELLS];   // [0]=dilated obstacle, [1]=explored

__device__ __forceinline__ void red_v4(float4* addr, float a, float b, float c, float d) {
    asm volatile("red.global.add.v4.f32 [%0], {%1, %2, %3, %4};"
                 :: "l"(addr), "f"(a), "f"(b), "f"(c), "f"(d) : "memory");
}

__global__ void scatter_kernel(const float* __restrict__ obs, float f_pix) {
    int idx = blockIdx.x * blockDim.x + threadIdx.x;
    if (idx >= NFRAMES * NPIX) return;
    int f   = idx / NPIX;
    int pix = idx - f * NPIX;
    int row = pix / DS_W;
    int col = pix - row * DS_W;

    const float* base = obs + (size_t)f * NCH * PLANE;
    int poff = (row * 4) * IMG_W + col * 4;

    // Streaming load (.cs): don't let the 84MB obs stream evict the 13MB acc from L2
    float depth = __ldcs(&base[3 * PLANE + poff]);
    if (!(depth > 20.0f && depth < 500.0f)) return;

    float uu = (float)(col * 4);
    float vv = (float)(row * 4);

    // Bit-exact binning: keep true divides (bin flips would be O(1) errors)
    float X  = __fdiv_rn((uu - 320.0f) * depth, f_pix);
    float Zh = 88.0f + __fdiv_rn((240.0f - vv) * depth, f_pix);

    int xb = __float2int_rn(__fdiv_rn(X, 5.0f) + 50.0f);
    int yb = __float2int_rn(__fdiv_rn(depth, 5.0f));
    int zb = __float2int_rn(__fdiv_rn(Zh, 5.0f)) + 8;

    if (xb < 0 || xb >= VR || yb < 0 || yb >= VR || zb < 0 || zb >= 80) return;

    int cell = yb * VR + xb;

    // Batch all 16 semantic plane loads (max MLP) before the atomics
    float s[NSEM];
    #pragma unroll
    for (int c = 0; c < NSEM; c++)
        s[c] = __ldcs(&base[(4 + c) * PLANE + poff]);

    // explored indicator: idempotent plain store
    g_ind[f][1][cell] = 1.0f;

    // obstacle: write dilated (3x3, clamped) indicator directly — idempotent
    if (zb >= MIN_MAPPED && zb < MAX_MAPPED) {
        int y0 = yb > 0 ? yb - 1 : 0, y1 = yb < VR - 1 ? yb + 1 : VR - 1;
        int x0 = xb > 0 ? xb - 1 : 0, x1 = xb < VR - 1 ? xb + 1 : VR - 1;
        for (int yy = y0; yy <= y1; yy++)
            for (int xx = x0; xx <= x1; xx++)
                g_ind[f][0][yy * VR + xx] = 1.0f;
    }

    // 16 semantic adds as 4 vector reductions into planar float4 planes
    red_v4(&g_sem[f][0][cell], s[0],  s[1],  s[2],  s[3]);
    red_v4(&g_sem[f][1][cell], s[4],  s[5],  s[6],  s[7]);
    red_v4(&g_sem[f][2][cell], s[8],  s[9],  s[10], s[11]);
    red_v4(&g_sem[f][3][cell], s[12], s[13], s[14], s[15]);
}

__device__ __forceinline__ float clip02(float x) {
    // x*0.2f differs from x/5 by <=1 ULP; output-only, far under 1e-3 tol
    return fminf(fmaxf(__fmul_rn(x, 0.2f), 0.0f), 1.0f);
}

// Thread per (frame, group, cell-pair). Groups 0..3 = sem float4 planes,
// group 4 = the two indicator planes. Each thread: 2 independent coalesced
// loads, fused zero-reset, coalesced planar output stores.
__global__ void __launch_bounds__(256) finalize_kernel(float* __restrict__ out) {
    int idx = blockIdx.x * blockDim.x + threadIdx.x;
    if (idx >= NFRAMES * 5 * HALF) return;
    int p   = idx % HALF;
    int rem = idx / HALF;
    int g   = rem % 5;
    int f   = rem / 5;

    float* dst = out + (size_t)f * NOUT * CELLS;
    const float4 z4 = make_float4(0.f, 0.f, 0.f, 0.f);

    if (g < 4) {
        float4 a = g_sem[f][g][p];
        float4 b = g_sem[f][g][p + HALF];
        g_sem[f][g][p]        = z4;
        g_sem[f][g][p + HALF] = z4;

        float* d = dst + (2 + 4 * g) * CELLS;
        d[p]         = clip02(a.x);  d[p + HALF]           = clip02(b.x);
        d[CELLS+p]   = clip02(a.y);  d[CELLS + p + HALF]   = clip02(b.y);
        d[2*CELLS+p] = clip02(a.z);  d[2*CELLS + p + HALF] = clip02(b.z);
        d[3*CELLS+p] = clip02(a.w);  d[3*CELLS + p + HALF] = clip02(b.w);
    } else {
        float ob0 = g_ind[f][0][p], ob1 = g_ind[f][0][p + HALF];
        float ex0 = g_ind[f][1][p], ex1 = g_ind[f][1][p + HALF];
        g_ind[f][0][p] = 0.0f;  g_ind[f][0][p + HALF] = 0.0f;
        g_ind[f][1][p] = 0.0f;  g_ind[f][1][p + HALF] = 0.0f;

        dst[p]                = ob0;   // obstacle (already dilated, {0,1})
        dst[p + HALF]         = ob1;
        dst[CELLS + p]        = ex0;   // explored (EXP_T=1 -> identity)
        dst[CELLS + p + HALF] = ex1;
    }
}

extern "C" void kernel_launch(void* const* d_in, const int* in_sizes, int n_in,
                              void* d_out, int out_size) {
    const float* obs = (const float*)d_in[0];   // (4,4,20,480,640) f32
    float* out = (float*)d_out;                 // (4,4,18,100,100) f32

    float f_pix = (float)(320.0 / tan(39.5 * 3.14159265358979323846 / 180.0));

    scatter_kernel<<<(NFRAMES * NPIX + 255) / 256, 256>>>(obs, f_pix);
    finalize_kernel<<<(NFRAMES * 5 * HALF + 255) / 256, 256>>>(out);
}

// round 10
// speedup vs baseline: 1.2465x; 1.2465x over previous
#include <cuda_runtime.h>
#include <math.h>

#define NFRAMES 16
#define IMG_H   480
#define IMG_W   640
#define NCH     20
#define PLANE   (IMG_H * IMG_W)
#define DS_H    120
#define DS_W    160
#define NPIX    (DS_H * DS_W)
#define VR      100
#define CELLS   (VR * VR)
#define NSEM    16
#define NOUT    (2 + NSEM)
#define MIN_MAPPED 13
#define MAX_MAPPED 25

// Planar-by-group accumulators. Statically zero-initialized; finalize restores
// zeros each launch (invariant: acc is all-zero on entry to kernel_launch).
__device__ float4 g_sem[NFRAMES][4][CELLS];   // [g] = sem channels 4g..4g+3
__device__ float  g_ind[NFRAMES][2][CELLS];   // [0]=dilated obstacle, [1]=explored

__device__ __forceinline__ void red_v4(float4* addr, float a, float b, float c, float d) {
    asm volatile("red.global.add.v4.f32 [%0], {%1, %2, %3, %4};"
                 :: "l"(addr), "f"(a), "f"(b), "f"(c), "f"(d) : "memory");
}

__global__ void scatter_kernel(const float* __restrict__ obs, float f_pix) {
    int idx = blockIdx.x * blockDim.x + threadIdx.x;
    if (idx >= NFRAMES * NPIX) return;
    int f   = idx / NPIX;
    int pix = idx - f * NPIX;
    int row = pix / DS_W;
    int col = pix - row * DS_W;

    const float* base = obs + (size_t)f * NCH * PLANE;
    int poff = (row * 4) * IMG_W + col * 4;

    // Streaming load (.cs): keep the obs stream from evicting the 13MB acc from L2
    float depth = __ldcs(&base[3 * PLANE + poff]);
    if (!(depth > 20.0f && depth < 500.0f)) return;

    float uu = (float)(col * 4);
    float vv = (float)(row * 4);

    // Bit-exact binning: keep true divides (bin flips would be O(1) errors)
    float X  = __fdiv_rn((uu - 320.0f) * depth, f_pix);
    float Zh = 88.0f + __fdiv_rn((240.0f - vv) * depth, f_pix);

    int xb = __float2int_rn(__fdiv_rn(X, 5.0f) + 50.0f);
    int yb = __float2int_rn(__fdiv_rn(depth, 5.0f));
    int zb = __float2int_rn(__fdiv_rn(Zh, 5.0f)) + 8;

    if (xb < 0 || xb >= VR || yb < 0 || yb >= VR || zb < 0 || zb >= 80) return;

    int cell = yb * VR + xb;

    // Batch all 16 semantic plane loads (max MLP) before the atomics
    float s[NSEM];
    #pragma unroll
    for (int c = 0; c < NSEM; c++)
        s[c] = __ldcs(&base[(4 + c) * PLANE + poff]);

    // explored indicator: idempotent plain store
    g_ind[f][1][cell] = 1.0f;

    // obstacle: write dilated (3x3, clamped) indicator directly — idempotent
    if (zb >= MIN_MAPPED && zb < MAX_MAPPED) {
        int y0 = yb > 0 ? yb - 1 : 0, y1 = yb < VR - 1 ? yb + 1 : VR - 1;
        int x0 = xb > 0 ? xb - 1 : 0, x1 = xb < VR - 1 ? xb + 1 : VR - 1;
        for (int yy = y0; yy <= y1; yy++)
            for (int xx = x0; xx <= x1; xx++)
                g_ind[f][0][yy * VR + xx] = 1.0f;
    }

    // 16 semantic adds as 4 vector reductions into planar float4 planes
    red_v4(&g_sem[f][0][cell], s[0],  s[1],  s[2],  s[3]);
    red_v4(&g_sem[f][1][cell], s[4],  s[5],  s[6],  s[7]);
    red_v4(&g_sem[f][2][cell], s[8],  s[9],  s[10], s[11]);
    red_v4(&g_sem[f][3][cell], s[12], s[13], s[14], s[15]);
}

// Thread per cell (R7 form — measured best structure); all loads/stores
// lane-coalesced in the planar layout; fused zero-reset.
__global__ void __launch_bounds__(256) finalize_kernel(float* __restrict__ out) {
    int idx = blockIdx.x * blockDim.x + threadIdx.x;
    if (idx >= NFRAMES * CELLS) return;
    int f    = idx / CELLS;
    int cell = idx - f * CELLS;

    float4 v0 = g_sem[f][0][cell];
    float4 v1 = g_sem[f][1][cell];
    float4 v2 = g_sem[f][2][cell];
    float4 v3 = g_sem[f][3][cell];
    float  ob = g_ind[f][0][cell];
    float  ex = g_ind[f][1][cell];

    // Fused reset (own addresses only -> race-free, coalesced)
    const float4 z = make_float4(0.f, 0.f, 0.f, 0.f);
    g_sem[f][0][cell] = z;
    g_sem[f][1][cell] = z;
    g_sem[f][2][cell] = z;
    g_sem[f][3][cell] = z;
    g_ind[f][0][cell] = 0.0f;
    g_ind[f][1][cell] = 0.0f;

    float* dst = out + (size_t)f * NOUT * CELLS + cell;
    dst[0]     = ob;   // obstacle (already dilated, {0,1})
    dst[CELLS] = ex;   // explored (EXP_T=1 -> identity)

    float sv[NSEM] = {v0.x,v0.y,v0.z,v0.w, v1.x,v1.y,v1.z,v1.w,
                      v2.x,v2.y,v2.z,v2.w, v3.x,v3.y,v3.z,v3.w};
    float* d = dst + 2 * CELLS;
    #pragma unroll
    for (int c = 0; c < NSEM; c++) {
        // x*0.2f differs from x/5 by <=1 ULP; output-only, far under 1e-3 tol
        d[0] = fminf(fmaxf(__fmul_rn(sv[c], 0.2f), 0.0f), 1.0f);
        d += CELLS;
    }
}

extern "C" void kernel_launch(void* const* d_in, const int* in_sizes, int n_in,
                              void* d_out, int out_size) {
    const float* obs = (const float*)d_in[0];   // (4,4,20,480,640) f32
    float* out = (float*)d_out;                 // (4,4,18,100,100) f32

    float f_pix = (float)(320.0 / tan(39.5 * 3.14159265358979323846 / 180.0));

    scatter_kernel<<<(NFRAMES * NPIX + 255) / 256, 256>>>(obs, f_pix);
    finalize_kernel<<<(NFRAMES * CELLS + 255) / 256, 256>>>(out);
}